// round 4
// baseline (speedup 1.0000x reference)
#include <cuda_runtime.h>
#include <mma.h>
#include <math.h>

using namespace nvcuda;

#define BATCH 16
#define SEQ   2048
#define HD    128

// Scratch: E = exp(masked score), per-(b,k) column sums. __device__ globals are
// the sanctioned scratch mechanism (no cudaMalloc allowed).
__device__ float g_E[(size_t)BATCH * SEQ * SEQ];     // 256 MB
__device__ float g_colsum[BATCH * SEQ];              // 128 KB
__device__ int   g_mask_is_u8;                       // 1 if mask buffer is 1-byte/elem

// ---------------------------------------------------------------------------
// K0a: detect mask dtype. int32 bool mask -> every word is 0 or 1.
// uint8 bool mask read as int32 -> words like 0x01010101 appear w.p. ~7/8/word.
// Scans 16384 words (64 KB, safely inside the >=67 MB mask buffer either way).
// Deterministic: same input -> same flag, rewritten on every replay.
// ---------------------------------------------------------------------------
__global__ void detect_mask_kernel(const int* __restrict__ mask_as_int) {
    __shared__ int bad;
    if (threadIdx.x == 0) bad = 0;
    __syncthreads();
    int v = mask_as_int[blockIdx.x * blockDim.x + threadIdx.x];
    if ((unsigned)v > 1u) bad = 1;          // benign shared race: any writer sets 1
    __syncthreads();
    if (threadIdx.x == 0 && bad) g_mask_is_u8 = 1;
}

__global__ void zero_colsum_kernel() {
    int i = blockIdx.x * blockDim.x + threadIdx.x;
    if (i == 0) g_mask_is_u8 = 0;           // reset before detection each replay
    if (i < BATCH * SEQ) g_colsum[i] = 0.0f;
}

// ---------------------------------------------------------------------------
// K1: E[b,q,k] = exp( mask ? 1e-9 : (Q.K^T)/sqrt(D) ),  colsum[b,k] += E
// Tile: 128(q) x 64(k), full D via chunks of 32. 8 warps, warp tile 32x32.
// tf32 wmma m16n16k8.
// ---------------------------------------------------------------------------
constexpr int BM = 128, BN = 64, BK = 32;
constexpr int C_LD = 72;   // 72*4B = 288B, multiple of 32B for wmma alignment

union SmemK1 {
    struct { float q[BM][BK]; float k[BN][BK]; } ab;   // 24 KB
    float c[BM][C_LD];                                 // 36.9 KB
};

__global__ __launch_bounds__(256) void qk_exp_kernel(
    const float* __restrict__ Q,
    const float* __restrict__ K,
    const void* __restrict__ mask)
{
    __shared__ SmemK1 sm;
    __shared__ float csum[BN];

    const int b  = blockIdx.z;
    const int q0 = blockIdx.y * BM;
    const int k0 = blockIdx.x * BN;
    const int tid  = threadIdx.x;
    const int warp = tid >> 5;
    const int warp_m = warp >> 1;   // 0..3 -> 32-row slice
    const int warp_n = warp & 1;    // 0..1 -> 32-col slice

    wmma::fragment<wmma::accumulator, 16, 16, 8, float> acc[2][2];
    #pragma unroll
    for (int i = 0; i < 2; i++)
        #pragma unroll
        for (int j = 0; j < 2; j++)
            wmma::fill_fragment(acc[i][j], 0.0f);

    const float* Qb = Q + ((size_t)b * SEQ + q0) * HD;
    const float* Kb = K + ((size_t)b * SEQ + k0) * HD;

    for (int dc = 0; dc < HD; dc += BK) {
        // Load Q chunk 128x32 (1024 float4, 4 per thread), convert to tf32
        #pragma unroll
        for (int it = 0; it < 4; it++) {
            int idx = tid + it * 256;
            int r = idx >> 3, c4 = (idx & 7) << 2;
            float4 v = *reinterpret_cast<const float4*>(&Qb[(size_t)r * HD + dc + c4]);
            float4 w;
            w.x = wmma::__float_to_tf32(v.x); w.y = wmma::__float_to_tf32(v.y);
            w.z = wmma::__float_to_tf32(v.z); w.w = wmma::__float_to_tf32(v.w);
            *reinterpret_cast<float4*>(&sm.ab.q[r][c4]) = w;
        }
        // Load K chunk 64x32 (512 float4, 2 per thread)
        #pragma unroll
        for (int it = 0; it < 2; it++) {
            int idx = tid + it * 256;
            int r = idx >> 3, c4 = (idx & 7) << 2;
            float4 v = *reinterpret_cast<const float4*>(&Kb[(size_t)r * HD + dc + c4]);
            float4 w;
            w.x = wmma::__float_to_tf32(v.x); w.y = wmma::__float_to_tf32(v.y);
            w.z = wmma::__float_to_tf32(v.z); w.w = wmma::__float_to_tf32(v.w);
            *reinterpret_cast<float4*>(&sm.ab.k[r][c4]) = w;
        }
        __syncthreads();

        #pragma unroll
        for (int kk = 0; kk < BK; kk += 8) {
            wmma::fragment<wmma::matrix_a, 16, 16, 8, wmma::precision::tf32, wmma::row_major> af[2];
            wmma::fragment<wmma::matrix_b, 16, 16, 8, wmma::precision::tf32, wmma::col_major> bf[2];
            #pragma unroll
            for (int i = 0; i < 2; i++)
                wmma::load_matrix_sync(af[i], &sm.ab.q[warp_m * 32 + i * 16][kk], BK);
            #pragma unroll
            for (int j = 0; j < 2; j++)
                wmma::load_matrix_sync(bf[j], &sm.ab.k[warp_n * 32 + j * 16][kk], BK);
            #pragma unroll
            for (int i = 0; i < 2; i++)
                #pragma unroll
                for (int j = 0; j < 2; j++)
                    wmma::mma_sync(acc[i][j], af[i], bf[j], acc[i][j]);
        }
        __syncthreads();
    }

    // Stage accumulators to shared (aliases the A/B buffers — synced above)
    #pragma unroll
    for (int i = 0; i < 2; i++)
        #pragma unroll
        for (int j = 0; j < 2; j++)
            wmma::store_matrix_sync(&sm.c[warp_m * 32 + i * 16][warp_n * 32 + j * 16],
                                    acc[i][j], C_LD, wmma::mem_row_major);
    if (tid < BN) csum[tid] = 0.0f;
    __syncthreads();

    const float scale = 0.088388347648318447f;   // 1/sqrt(128)
    const size_t moff = ((size_t)b * SEQ + q0) * SEQ + k0;
    const int*           mbi = reinterpret_cast<const int*>(mask) + moff;
    const unsigned char* mb8 = reinterpret_cast<const unsigned char*>(mask) + moff;
    const bool is_u8 = (g_mask_is_u8 != 0);
    float* Eb = g_E + moff;

    #pragma unroll
    for (int it = 0; it < (BM * BN) / 256; it++) {
        int idx = tid + it * 256;
        int r = idx / BN, c = idx % BN;
        float s = sm.c[r][c] * scale;
        int m = is_u8 ? (int)mb8[(size_t)r * SEQ + c] : mbi[(size_t)r * SEQ + c];
        float v = m ? 1e-9f : s;
        float e = expf(v);
        Eb[(size_t)r * SEQ + c] = e;
        atomicAdd(&csum[c], e);
    }
    __syncthreads();
    if (tid < BN) atomicAdd(&g_colsum[b * SEQ + k0 + tid], csum[tid]);
}

// ---------------------------------------------------------------------------
// K2: out[b,q,d] = sum_k (E[b,q,k]/colsum[b,k]) * V[b,k,d]
// Tile: 128(q) x 128(d), k chunks of 32. 8 warps, warp tile 64x32.
// ---------------------------------------------------------------------------
constexpr int BM3 = 128, BK3 = 32;
constexpr int E_LD = 40;    // 160B rows, 32B-multiple
constexpr int V_LD = 136;   // 544B rows, 32B-multiple

__global__ __launch_bounds__(256) void pv_kernel(
    const float* __restrict__ V,
    float* __restrict__ out)
{
    __shared__ float Es[BM3][E_LD];
    __shared__ float Vs[BK3][V_LD];

    const int b  = blockIdx.y;
    const int q0 = blockIdx.x * BM3;
    const int tid  = threadIdx.x;
    const int warp = tid >> 5;
    const int warp_m = warp >> 2;   // 0..1 -> 64-row slice
    const int warp_n = warp & 3;    // 0..3 -> 32-col slice

    wmma::fragment<wmma::accumulator, 16, 16, 8, float> acc[4][2];
    #pragma unroll
    for (int i = 0; i < 4; i++)
        #pragma unroll
        for (int j = 0; j < 2; j++)
            wmma::fill_fragment(acc[i][j], 0.0f);

    const float* Eb = g_E + ((size_t)b * SEQ + q0) * SEQ;
    const float* Vb = V + (size_t)b * SEQ * HD;
    const float* cs = g_colsum + b * SEQ;

    for (int kc = 0; kc < SEQ; kc += BK3) {
        // E chunk 128x32
        #pragma unroll
        for (int it = 0; it < 4; it++) {
            int idx = tid + it * 256;
            int r = idx >> 3, c4 = (idx & 7) << 2;
            float4 v = *reinterpret_cast<const float4*>(&Eb[(size_t)r * SEQ + kc + c4]);
            float4 w;
            w.x = wmma::__float_to_tf32(v.x); w.y = wmma::__float_to_tf32(v.y);
            w.z = wmma::__float_to_tf32(v.z); w.w = wmma::__float_to_tf32(v.w);
            *reinterpret_cast<float4*>(&Es[r][c4]) = w;
        }
        // V chunk 32x128, scaled by 1/colsum[k]
        #pragma unroll
        for (int it = 0; it < 4; it++) {
            int idx = tid + it * 256;
            int r = idx >> 5, c4 = (idx & 31) << 2;
            float inv = 1.0f / cs[kc + r];
            float4 v = *reinterpret_cast<const float4*>(&Vb[(size_t)(kc + r) * HD + c4]);
            float4 w;
            w.x = wmma::__float_to_tf32(v.x * inv); w.y = wmma::__float_to_tf32(v.y * inv);
            w.z = wmma::__float_to_tf32(v.z * inv); w.w = wmma::__float_to_tf32(v.w * inv);
            *reinterpret_cast<float4*>(&Vs[r][c4]) = w;
        }
        __syncthreads();

        #pragma unroll
        for (int kk = 0; kk < BK3; kk += 8) {
            wmma::fragment<wmma::matrix_a, 16, 16, 8, wmma::precision::tf32, wmma::row_major> af[4];
            wmma::fragment<wmma::matrix_b, 16, 16, 8, wmma::precision::tf32, wmma::row_major> bf[2];
            #pragma unroll
            for (int i = 0; i < 4; i++)
                wmma::load_matrix_sync(af[i], &Es[warp_m * 64 + i * 16][kk], E_LD);
            #pragma unroll
            for (int j = 0; j < 2; j++)
                wmma::load_matrix_sync(bf[j], &Vs[kk][warp_n * 32 + j * 16], V_LD);
            #pragma unroll
            for (int i = 0; i < 4; i++)
                #pragma unroll
                for (int j = 0; j < 2; j++)
                    wmma::mma_sync(acc[i][j], af[i], bf[j], acc[i][j]);
        }
        __syncthreads();
    }

    // Store accumulators straight to global (fp32 out, row stride = HD)
    #pragma unroll
    for (int i = 0; i < 4; i++)
        #pragma unroll
        for (int j = 0; j < 2; j++) {
            float* dst = out + ((size_t)b * SEQ + q0 + warp_m * 64 + i * 16) * HD
                             + warp_n * 32 + j * 16;
            wmma::store_matrix_sync(dst, acc[i][j], HD, wmma::mem_row_major);
        }
}

// ---------------------------------------------------------------------------
extern "C" void kernel_launch(void* const* d_in, const int* in_sizes, int n_in,
                              void* d_out, int out_size) {
    const float* Q = (const float*)d_in[0];
    const float* K = (const float*)d_in[1];
    const float* V = (const float*)d_in[2];
    const void*  mask = d_in[3];
    float* out = (float*)d_out;

    zero_colsum_kernel<<<(BATCH * SEQ + 255) / 256, 256>>>();
    detect_mask_kernel<<<64, 256>>>((const int*)mask);   // scans 64 KB
    qk_exp_kernel<<<dim3(SEQ / BN, SEQ / BM, BATCH), 256>>>(Q, K, mask);
    pv_kernel<<<dim3(SEQ / BM3, BATCH), 256>>>(V, out);
}

// round 6
// speedup vs baseline: 1.4393x; 1.4393x over previous
#include <cuda_runtime.h>
#include <mma.h>
#include <math.h>
#include <stdint.h>

using namespace nvcuda;

#define BATCH 16
#define SEQ   2048
#define HD    128

// ---------------- scratch (__device__ globals: the sanctioned mechanism) ----
__device__ float g_E[(size_t)BATCH * SEQ * SEQ];     // 256 MB, tf32-rounded exp scores
__device__ float g_colsum[BATCH * SEQ];              // per-(b,k) column sums
__device__ int   g_mask_is_u8;
__device__ float g_Qt[BATCH * SEQ * HD];             // tf32-rounded Q
__device__ float g_Kt[BATCH * SEQ * HD];             // tf32-rounded K
__device__ float g_Vt[BATCH * SEQ * HD];             // tf32-rounded V / colsum

// ---------------- cp.async helpers ----------------------------------------
__device__ __forceinline__ void cp16(float* smem_dst, const float* gsrc) {
    uint32_t s = (uint32_t)__cvta_generic_to_shared(smem_dst);
    asm volatile("cp.async.cg.shared.global [%0], [%1], 16;" :: "r"(s), "l"(gsrc));
}
__device__ __forceinline__ void cp_commit() {
    asm volatile("cp.async.commit_group;" ::: "memory");
}
template<int N> __device__ __forceinline__ void cp_wait() {
    asm volatile("cp.async.wait_group %0;" :: "n"(N) : "memory");
}

// ---------------- K0: zero colsum + reset flag -----------------------------
__global__ void zero_colsum_kernel() {
    int i = blockIdx.x * blockDim.x + threadIdx.x;
    if (i == 0) g_mask_is_u8 = 0;
    if (i < BATCH * SEQ) g_colsum[i] = 0.0f;
}

// ---------------- K0b: mask dtype detection (int32 bool -> words in {0,1}) -
__global__ void detect_mask_kernel(const int* __restrict__ mask_as_int) {
    __shared__ int bad;
    if (threadIdx.x == 0) bad = 0;
    __syncthreads();
    int v = mask_as_int[blockIdx.x * blockDim.x + threadIdx.x];
    if ((unsigned)v > 1u) bad = 1;
    __syncthreads();
    if (threadIdx.x == 0 && bad) g_mask_is_u8 = 1;
}

// ---------------- prologue: round fp32 -> tf32 in scratch ------------------
__global__ void cvt_tf32_kernel(const float4* __restrict__ src, int dst_sel) {
    int i = blockIdx.x * blockDim.x + threadIdx.x;   // float4 index
    float4 v = src[i];
    v.x = wmma::__float_to_tf32(v.x); v.y = wmma::__float_to_tf32(v.y);
    v.z = wmma::__float_to_tf32(v.z); v.w = wmma::__float_to_tf32(v.w);
    float4* dst = reinterpret_cast<float4*>(dst_sel ? g_Kt : g_Qt);
    dst[i] = v;
}

// ---------------- between GEMMs: Vt = tf32(V / colsum) ---------------------
__global__ void scale_v_kernel(const float4* __restrict__ V) {
    int i = blockIdx.x * blockDim.x + threadIdx.x;   // float4 index
    int row = i >> 5;                                // (b*SEQ + k), 32 float4 per row
    float inv = 1.0f / g_colsum[row];
    float4 v = V[i];
    v.x = wmma::__float_to_tf32(v.x * inv); v.y = wmma::__float_to_tf32(v.y * inv);
    v.z = wmma::__float_to_tf32(v.z * inv); v.w = wmma::__float_to_tf32(v.w * inv);
    reinterpret_cast<float4*>(g_Vt)[i] = v;
}

// ---------------------------------------------------------------------------
// K1: E[b,q,k] = tf32(exp( mask ? 1e-9 : (Q.K^T)/sqrt(D) )), colsum[b,k] += E
// 128(q) x 64(k) tile, 4 K-chunks of 32, 2-stage cp.async pipeline.
// ---------------------------------------------------------------------------
constexpr int BM = 128, BN = 64, BK = 32;
constexpr int LDA1   = 36;                 // padded row stride (floats)
constexpr int STAGE1 = (BM + BN) * LDA1;   // 6912 floats per stage
constexpr int SMEM1  = STAGE1 * 2 * 4;     // 55296 bytes
constexpr int C_LD   = 72;

__global__ __launch_bounds__(256, 2) void qk_exp_kernel(const void* __restrict__ mask)
{
    extern __shared__ float dsm[];
    __shared__ float csum[BN];

    const int b  = blockIdx.z;
    const int q0 = blockIdx.y * BM;
    const int k0 = blockIdx.x * BN;
    const int tid  = threadIdx.x;
    const int warp = tid >> 5;
    const int warp_m = warp >> 1;
    const int warp_n = warp & 1;

    const float* Qb = g_Qt + ((size_t)b * SEQ + q0) * HD;
    const float* Kb = g_Kt + ((size_t)b * SEQ + k0) * HD;

    wmma::fragment<wmma::accumulator, 16, 16, 8, float> acc[2][2];
    #pragma unroll
    for (int i = 0; i < 2; i++)
        #pragma unroll
        for (int j = 0; j < 2; j++)
            wmma::fill_fragment(acc[i][j], 0.0f);

    auto load_stage = [&](int s, int dc) {
        float* qs = dsm + s * STAGE1;
        float* ks = qs + BM * LDA1;
        #pragma unroll
        for (int it = 0; it < 4; it++) {                 // Q 128x32 = 1024 f4
            int idx = tid + it * 256;
            int r = idx >> 3, c4 = (idx & 7) << 2;
            cp16(qs + r * LDA1 + c4, Qb + (size_t)r * HD + dc + c4);
        }
        #pragma unroll
        for (int it = 0; it < 2; it++) {                 // K 64x32 = 512 f4
            int idx = tid + it * 256;
            int r = idx >> 3, c4 = (idx & 7) << 2;
            cp16(ks + r * LDA1 + c4, Kb + (size_t)r * HD + dc + c4);
        }
    };

    load_stage(0, 0); cp_commit();
    for (int c = 0; c < 4; c++) {
        if (c < 3) { load_stage((c + 1) & 1, (c + 1) * BK); cp_commit(); cp_wait<1>(); }
        else       { cp_wait<0>(); }
        __syncthreads();

        float* qs = dsm + (c & 1) * STAGE1;
        float* ks = qs + BM * LDA1;
        #pragma unroll
        for (int kk = 0; kk < BK; kk += 8) {
            wmma::fragment<wmma::matrix_a, 16, 16, 8, wmma::precision::tf32, wmma::row_major> af[2];
            wmma::fragment<wmma::matrix_b, 16, 16, 8, wmma::precision::tf32, wmma::col_major> bf[2];
            #pragma unroll
            for (int i = 0; i < 2; i++)
                wmma::load_matrix_sync(af[i], qs + (warp_m * 32 + i * 16) * LDA1 + kk, LDA1);
            #pragma unroll
            for (int j = 0; j < 2; j++)
                wmma::load_matrix_sync(bf[j], ks + (warp_n * 32 + j * 16) * LDA1 + kk, LDA1);
            #pragma unroll
            for (int i = 0; i < 2; i++)
                #pragma unroll
                for (int j = 0; j < 2; j++)
                    wmma::mma_sync(acc[i][j], af[i], bf[j], acc[i][j]);
        }
        __syncthreads();
    }

    // Stage accumulators into smem (stage buffers are dead now)
    float* C = dsm;
    #pragma unroll
    for (int i = 0; i < 2; i++)
        #pragma unroll
        for (int j = 0; j < 2; j++)
            wmma::store_matrix_sync(C + (warp_m * 32 + i * 16) * C_LD + warp_n * 32 + j * 16,
                                    acc[i][j], C_LD, wmma::mem_row_major);
    if (tid < BN) csum[tid] = 0.0f;
    __syncthreads();

    const float scale = 0.088388347648318447f;   // 1/sqrt(128)
    const size_t moff = ((size_t)b * SEQ + q0) * SEQ + k0;
    const int*           mbi = reinterpret_cast<const int*>(mask) + moff;
    const unsigned char* mb8 = reinterpret_cast<const unsigned char*>(mask) + moff;
    const bool is_u8 = (g_mask_is_u8 != 0);
    float* Eb = g_E + moff;

    #pragma unroll
    for (int it = 0; it < (BM * BN) / 256; it++) {
        int idx = tid + it * 256;
        int r = idx / BN, c = idx % BN;
        float s = C[r * C_LD + c] * scale;
        int m = is_u8 ? (int)mb8[(size_t)r * SEQ + c] : mbi[(size_t)r * SEQ + c];
        float v = m ? 1e-9f : s;
        float e = wmma::__float_to_tf32(expf(v));   // pre-round: K2 consumes raw
        Eb[(size_t)r * SEQ + c] = e;
        atomicAdd(&csum[c], e);
    }
    __syncthreads();
    if (tid < BN) atomicAdd(&g_colsum[b * SEQ + k0 + tid], csum[tid]);
}

// ---------------------------------------------------------------------------
// K2: out[b,q,d] = sum_k E[b,q,k] * Vt[b,k,d]    (Vt pre-scaled by 1/colsum)
// 128(q) x 128(d) tile, 64 K-chunks of 32, 2-stage cp.async pipeline.
// ---------------------------------------------------------------------------
constexpr int BM3 = 128, BK3 = 32;
constexpr int LDE    = 36;
constexpr int LDV    = 132;
constexpr int STAGE2 = BM3 * LDE + BK3 * LDV;   // 8832 floats
constexpr int SMEM2  = STAGE2 * 2 * 4;          // 70656 bytes

__global__ __launch_bounds__(256, 2) void pv_kernel(float* __restrict__ out)
{
    extern __shared__ float dsm[];

    const int b  = blockIdx.y;
    const int q0 = blockIdx.x * BM3;
    const int tid  = threadIdx.x;
    const int warp = tid >> 5;
    const int warp_m = warp >> 2;   // 0..1 -> 64 rows
    const int warp_n = warp & 3;    // 0..3 -> 32 cols

    const float* Eb = g_E + ((size_t)b * SEQ + q0) * SEQ;
    const float* Vb = g_Vt + (size_t)b * SEQ * HD;

    wmma::fragment<wmma::accumulator, 16, 16, 8, float> acc[4][2];
    #pragma unroll
    for (int i = 0; i < 4; i++)
        #pragma unroll
        for (int j = 0; j < 2; j++)
            wmma::fill_fragment(acc[i][j], 0.0f);

    auto load_stage = [&](int s, int kc) {
        float* Es = dsm + s * STAGE2;
        float* Vs = Es + BM3 * LDE;
        #pragma unroll
        for (int it = 0; it < 4; it++) {                 // E 128x32 = 1024 f4
            int idx = tid + it * 256;
            int r = idx >> 3, c4 = (idx & 7) << 2;
            cp16(Es + r * LDE + c4, Eb + (size_t)r * SEQ + kc + c4);
        }
        #pragma unroll
        for (int it = 0; it < 4; it++) {                 // V 32x128 = 1024 f4
            int idx = tid + it * 256;
            int r = idx >> 5, c4 = (idx & 31) << 2;
            cp16(Vs + r * LDV + c4, Vb + (size_t)(kc + r) * HD + c4);
        }
    };

    load_stage(0, 0); cp_commit();
    for (int c = 0; c < SEQ / BK3; c++) {
        if (c < SEQ / BK3 - 1) { load_stage((c + 1) & 1, (c + 1) * BK3); cp_commit(); cp_wait<1>(); }
        else                   { cp_wait<0>(); }
        __syncthreads();

        float* Es = dsm + (c & 1) * STAGE2;
        float* Vs = Es + BM3 * LDE;
        #pragma unroll
        for (int kk = 0; kk < BK3; kk += 8) {
            wmma::fragment<wmma::matrix_a, 16, 16, 8, wmma::precision::tf32, wmma::row_major> af[4];
            wmma::fragment<wmma::matrix_b, 16, 16, 8, wmma::precision::tf32, wmma::row_major> bf[2];
            #pragma unroll
            for (int i = 0; i < 4; i++)
                wmma::load_matrix_sync(af[i], Es + (warp_m * 64 + i * 16) * LDE + kk, LDE);
            #pragma unroll
            for (int j = 0; j < 2; j++)
                wmma::load_matrix_sync(bf[j], Vs + kk * LDV + warp_n * 32 + j * 16, LDV);
            #pragma unroll
            for (int i = 0; i < 4; i++)
                #pragma unroll
                for (int j = 0; j < 2; j++)
                    wmma::mma_sync(acc[i][j], af[i], bf[j], acc[i][j]);
        }
        __syncthreads();
    }

    #pragma unroll
    for (int i = 0; i < 4; i++)
        #pragma unroll
        for (int j = 0; j < 2; j++) {
            float* dst = out + ((size_t)b * SEQ + q0 + warp_m * 64 + i * 16) * HD
                             + warp_n * 32 + j * 16;
            wmma::store_matrix_sync(dst, acc[i][j], HD, wmma::mem_row_major);
        }
}

// ---------------------------------------------------------------------------
extern "C" void kernel_launch(void* const* d_in, const int* in_sizes, int n_in,
                              void* d_out, int out_size) {
    const float* Q = (const float*)d_in[0];
    const float* K = (const float*)d_in[1];
    const float* V = (const float*)d_in[2];
    const void*  mask = d_in[3];
    float* out = (float*)d_out;

    // Attribute set (idempotent, not an allocation, not a stream op)
    cudaFuncSetAttribute(qk_exp_kernel, cudaFuncAttributeMaxDynamicSharedMemorySize, SMEM1);
    cudaFuncSetAttribute(pv_kernel,     cudaFuncAttributeMaxDynamicSharedMemorySize, SMEM2);

    const int n4 = BATCH * SEQ * HD / 4;   // 1,048,576 float4

    zero_colsum_kernel<<<(BATCH * SEQ + 255) / 256, 256>>>();
    detect_mask_kernel<<<64, 256>>>((const int*)mask);
    cvt_tf32_kernel<<<n4 / 256, 256>>>((const float4*)Q, 0);
    cvt_tf32_kernel<<<n4 / 256, 256>>>((const float4*)K, 1);
    qk_exp_kernel<<<dim3(SEQ / BN, SEQ / BM, BATCH), 256, SMEM1>>>(mask);
    scale_v_kernel<<<n4 / 256, 256>>>((const float4*)V);
    pv_kernel<<<dim3(SEQ / BM3, BATCH), 256, SMEM2>>>(out);
}

// round 8
// speedup vs baseline: 5.6866x; 3.9509x over previous
#include <cuda_runtime.h>
#include <cuda_fp16.h>
#include <mma.h>
#include <math.h>
#include <stdint.h>

using namespace nvcuda;

#define BATCH 16
#define SEQ   2048
#define HD    128

// ---------------- scratch (__device__ globals) -----------------------------
__device__ __half g_Eh[(size_t)BATCH * SEQ * SEQ];   // 128 MB exp scores (fp16)
__device__ float  g_colsum[BATCH * SEQ];
__device__ int    g_mask_is_u8;
__device__ __half g_Qh[BATCH * SEQ * HD];
__device__ __half g_Kh[BATCH * SEQ * HD];
__device__ __half g_Vh[BATCH * SEQ * HD];            // V / colsum, fp16

// ---------------- cp.async helpers -----------------------------------------
__device__ __forceinline__ void cp16(void* smem_dst, const void* gsrc) {
    uint32_t s = (uint32_t)__cvta_generic_to_shared(smem_dst);
    asm volatile("cp.async.cg.shared.global [%0], [%1], 16;" :: "r"(s), "l"(gsrc));
}
__device__ __forceinline__ void cp_commit() {
    asm volatile("cp.async.commit_group;" ::: "memory");
}
template<int N> __device__ __forceinline__ void cp_wait() {
    asm volatile("cp.async.wait_group %0;" :: "n"(N) : "memory");
}

// ---------------- tiny prologues -------------------------------------------
__global__ void zero_colsum_kernel() {
    int i = blockIdx.x * blockDim.x + threadIdx.x;
    if (i == 0) g_mask_is_u8 = 0;
    if (i < BATCH * SEQ) g_colsum[i] = 0.0f;
}

// int32 bool mask -> every word in {0,1}; u8 mask read as int32 -> words like
// 0x01010101 with prob ~7/8 per word over 16K words.
__global__ void detect_mask_kernel(const int* __restrict__ mask_as_int) {
    __shared__ int bad;
    if (threadIdx.x == 0) bad = 0;
    __syncthreads();
    int v = mask_as_int[blockIdx.x * blockDim.x + threadIdx.x];
    if ((unsigned)v > 1u) bad = 1;
    __syncthreads();
    if (threadIdx.x == 0 && bad) g_mask_is_u8 = 1;
}

__global__ void cvt_half_kernel(const float4* __restrict__ src, int dst_sel) {
    int i = blockIdx.x * blockDim.x + threadIdx.x;   // float4 index
    float4 v = src[i];
    __half2* dst = reinterpret_cast<__half2*>(dst_sel ? g_Kh : g_Qh);
    dst[i * 2 + 0] = __floats2half2_rn(v.x, v.y);
    dst[i * 2 + 1] = __floats2half2_rn(v.z, v.w);
}

__global__ void scale_v_kernel(const float4* __restrict__ V) {
    int i = blockIdx.x * blockDim.x + threadIdx.x;   // float4 index
    int row = i >> 5;                                // (b*SEQ + k)
    float inv = 1.0f / g_colsum[row];
    float4 v = V[i];
    __half2* dst = reinterpret_cast<__half2*>(g_Vh);
    dst[i * 2 + 0] = __floats2half2_rn(v.x * inv, v.y * inv);
    dst[i * 2 + 1] = __floats2half2_rn(v.z * inv, v.w * inv);
}

// ---------------------------------------------------------------------------
// K1: Eh[b,q,k] = half(exp( mask ? 1e-9 : (Q.K^T)/sqrt(D) ))
//     colsum[b,k] += sum_q float(Eh)        (denominator matches numerators)
// Tile 128(q) x 128(k), full-depth resident fp16 operands, 8 warps 64x32.
// ---------------------------------------------------------------------------
constexpr int BM1 = 128, BN1 = 128;
constexpr int LD1 = 136;                        // halves; 272B rows, 16B-mult
constexpr int QS_H   = BM1 * LD1;               // 17408 halves
constexpr int SMEM1  = 2 * QS_H * 2;            // Q + K tiles = 69632 B
constexpr int C_LD   = 132;                     // fp32 staging stride

__global__ __launch_bounds__(256, 2) void qk_exp_kernel(const void* __restrict__ mask)
{
    extern __shared__ __half hsm[];
    __half* Qs = hsm;
    __half* Ks = hsm + QS_H;

    const int b  = blockIdx.z;
    const int q0 = blockIdx.y * BM1;
    const int k0 = blockIdx.x * BN1;
    const int tid  = threadIdx.x;
    const int warp = tid >> 5;
    const int warp_m = warp >> 2;   // 0..1 -> 64 q rows
    const int warp_n = warp & 3;    // 0..3 -> 32 k cols

    const __half* Qb = g_Qh + ((size_t)b * SEQ + q0) * HD;
    const __half* Kb = g_Kh + ((size_t)b * SEQ + k0) * HD;

    // Load both tiles: 128 rows x 128 halves = 16 x 16B chunks per row.
    #pragma unroll
    for (int it = 0; it < 8; it++) {
        int idx = tid + it * 256;
        int r = idx >> 4, c8 = (idx & 15) << 3;
        cp16(Qs + r * LD1 + c8, Qb + (size_t)r * HD + c8);
    }
    #pragma unroll
    for (int it = 0; it < 8; it++) {
        int idx = tid + it * 256;
        int r = idx >> 4, c8 = (idx & 15) << 3;
        cp16(Ks + r * LD1 + c8, Kb + (size_t)r * HD + c8);
    }
    cp_commit(); cp_wait<0>();
    __syncthreads();

    wmma::fragment<wmma::accumulator, 16, 16, 16, float> acc[4][2];
    #pragma unroll
    for (int i = 0; i < 4; i++)
        #pragma unroll
        for (int j = 0; j < 2; j++)
            wmma::fill_fragment(acc[i][j], 0.0f);

    #pragma unroll
    for (int kk = 0; kk < HD; kk += 16) {
        wmma::fragment<wmma::matrix_a, 16, 16, 16, __half, wmma::row_major> af[4];
        wmma::fragment<wmma::matrix_b, 16, 16, 16, __half, wmma::col_major> bf[2];
        #pragma unroll
        for (int i = 0; i < 4; i++)
            wmma::load_matrix_sync(af[i], Qs + (warp_m * 64 + i * 16) * LD1 + kk, LD1);
        #pragma unroll
        for (int j = 0; j < 2; j++)
            wmma::load_matrix_sync(bf[j], Ks + (warp_n * 32 + j * 16) * LD1 + kk, LD1);
        #pragma unroll
        for (int i = 0; i < 4; i++)
            #pragma unroll
            for (int j = 0; j < 2; j++)
                wmma::mma_sync(acc[i][j], af[i], bf[j], acc[i][j]);
    }
    __syncthreads();   // tiles dead; reuse smem for fp32 staging

    float* C = reinterpret_cast<float*>(hsm);
    #pragma unroll
    for (int i = 0; i < 4; i++)
        #pragma unroll
        for (int j = 0; j < 2; j++)
            wmma::store_matrix_sync(C + (warp_m * 64 + i * 16) * C_LD + warp_n * 32 + j * 16,
                                    acc[i][j], C_LD, wmma::mem_row_major);
    __syncthreads();

    // Epilogue: thread owns column c = tid & 127, rows r = (tid>>7) + 2*it.
    const float scale = 0.088388347648318447f;   // 1/sqrt(128)
    const size_t moff = ((size_t)b * SEQ + q0) * SEQ + k0;
    const int*           mbi = reinterpret_cast<const int*>(mask) + moff;
    const unsigned char* mb8 = reinterpret_cast<const unsigned char*>(mask) + moff;
    const bool is_u8 = (g_mask_is_u8 != 0);
    __half* Eb = g_Eh + moff;

    const int c  = tid & 127;
    const int r0 = tid >> 7;
    float local = 0.0f;
    #pragma unroll 8
    for (int it = 0; it < 64; it++) {
        int r = r0 + it * 2;
        float s = C[r * C_LD + c] * scale;
        int m = is_u8 ? (int)mb8[(size_t)r * SEQ + c] : mbi[(size_t)r * SEQ + c];
        float v = m ? 1e-9f : s;
        __half h = __float2half_rn(__expf(v));
        Eb[(size_t)r * SEQ + c] = h;
        local += __half2float(h);                // denominator = sum of numerators
    }
    atomicAdd(&g_colsum[b * SEQ + k0 + c], local);
}

// ---------------------------------------------------------------------------
// K2: out[b,q,d] = sum_k Eh[b,q,k] * Vh[b,k,d]   (Vh pre-scaled by 1/colsum)
// Tile 128(q) x 128(d), K chunks of 64, 2-stage cp.async, 8 warps 64x32.
// ---------------------------------------------------------------------------
constexpr int BM2 = 128, BK2 = 64;
constexpr int LDE2 = 72;                         // halves
constexpr int LDV2 = 136;                        // halves
constexpr int ST2_H  = BM2 * LDE2 + BK2 * LDV2;  // 17920 halves per stage
constexpr int SMEM2  = ST2_H * 2 * 2;            // 71680 B

__global__ __launch_bounds__(256, 2) void pv_kernel(float* __restrict__ out)
{
    extern __shared__ __half hsm[];

    const int b  = blockIdx.y;
    const int q0 = blockIdx.x * BM2;
    const int tid  = threadIdx.x;
    const int warp = tid >> 5;
    const int warp_m = warp >> 2;   // 0..1 -> 64 q rows
    const int warp_n = warp & 3;    // 0..3 -> 32 d cols

    const __half* Eb = g_Eh + ((size_t)b * SEQ + q0) * SEQ;
    const __half* Vb = g_Vh + (size_t)b * SEQ * HD;

    wmma::fragment<wmma::accumulator, 16, 16, 16, float> acc[4][2];
    #pragma unroll
    for (int i = 0; i < 4; i++)
        #pragma unroll
        for (int j = 0; j < 2; j++)
            wmma::fill_fragment(acc[i][j], 0.0f);

    auto load_stage = [&](int s, int kc) {
        __half* Es = hsm + s * ST2_H;
        __half* Vs = Es + BM2 * LDE2;
        #pragma unroll
        for (int it = 0; it < 4; it++) {               // E 128 x 64 halves
            int idx = tid + it * 256;
            int r = idx >> 3, c8 = (idx & 7) << 3;
            cp16(Es + r * LDE2 + c8, Eb + (size_t)r * SEQ + kc + c8);
        }
        #pragma unroll
        for (int it = 0; it < 4; it++) {               // V 64 x 128 halves
            int idx = tid + it * 256;
            int r = idx >> 4, c8 = (idx & 15) << 3;
            cp16(Vs + r * LDV2 + c8, Vb + (size_t)(kc + r) * HD + c8);
        }
    };

    load_stage(0, 0); cp_commit();
    for (int c = 0; c < SEQ / BK2; c++) {
        if (c < SEQ / BK2 - 1) { load_stage((c + 1) & 1, (c + 1) * BK2); cp_commit(); cp_wait<1>(); }
        else                   { cp_wait<0>(); }
        __syncthreads();

        __half* Es = hsm + (c & 1) * ST2_H;
        __half* Vs = Es + BM2 * LDE2;
        #pragma unroll
        for (int kk = 0; kk < BK2; kk += 16) {
            wmma::fragment<wmma::matrix_a, 16, 16, 16, __half, wmma::row_major> af[4];
            wmma::fragment<wmma::matrix_b, 16, 16, 16, __half, wmma::row_major> bf[2];
            #pragma unroll
            for (int i = 0; i < 4; i++)
                wmma::load_matrix_sync(af[i], Es + (warp_m * 64 + i * 16) * LDE2 + kk, LDE2);
            #pragma unroll
            for (int j = 0; j < 2; j++)
                wmma::load_matrix_sync(bf[j], Vs + kk * LDV2 + warp_n * 32 + j * 16, LDV2);
            #pragma unroll
            for (int i = 0; i < 4; i++)
                #pragma unroll
                for (int j = 0; j < 2; j++)
                    wmma::mma_sync(acc[i][j], af[i], bf[j], acc[i][j]);
        }
        __syncthreads();
    }

    #pragma unroll
    for (int i = 0; i < 4; i++)
        #pragma unroll
        for (int j = 0; j < 2; j++) {
            float* dst = out + ((size_t)b * SEQ + q0 + warp_m * 64 + i * 16) * HD
                             + warp_n * 32 + j * 16;
            wmma::store_matrix_sync(dst, acc[i][j], HD, wmma::mem_row_major);
        }
}

// ---------------------------------------------------------------------------
extern "C" void kernel_launch(void* const* d_in, const int* in_sizes, int n_in,
                              void* d_out, int out_size) {
    const float* Q = (const float*)d_in[0];
    const float* K = (const float*)d_in[1];
    const float* V = (const float*)d_in[2];
    const void*  mask = d_in[3];
    float* out = (float*)d_out;

    cudaFuncSetAttribute(qk_exp_kernel, cudaFuncAttributeMaxDynamicSharedMemorySize, SMEM1);
    cudaFuncSetAttribute(pv_kernel,     cudaFuncAttributeMaxDynamicSharedMemorySize, SMEM2);

    const int n4 = BATCH * SEQ * HD / 4;   // float4 count

    zero_colsum_kernel<<<(BATCH * SEQ + 255) / 256, 256>>>();
    detect_mask_kernel<<<64, 256>>>((const int*)mask);
    cvt_half_kernel<<<n4 / 256, 256>>>((const float4*)Q, 0);
    cvt_half_kernel<<<n4 / 256, 256>>>((const float4*)K, 1);
    qk_exp_kernel<<<dim3(SEQ / BN1, SEQ / BM1, BATCH), 256, SMEM1>>>(mask);
    scale_v_kernel<<<n4 / 256, 256>>>((const float4*)V);
    pv_kernel<<<dim3(SEQ / BM2, BATCH), 256, SMEM2>>>(out);
}

// round 10
// speedup vs baseline: 7.2357x; 1.2724x over previous
#include <cuda_runtime.h>
#include <cuda_fp16.h>
#include <mma.h>
#include <math.h>
#include <stdint.h>

using namespace nvcuda;

#define BATCH 16
#define SEQ   2048
#define HD    128

// ---------------- scratch (__device__ globals) -----------------------------
__device__ __half g_Eh[(size_t)BATCH * SEQ * SEQ];   // 128 MB exp scores (fp16)
__device__ float  g_colsum[BATCH * SEQ];
__device__ int    g_mask_is_u8;
__device__ __half g_Qh[BATCH * SEQ * HD];
__device__ __half g_Kh[BATCH * SEQ * HD];
__device__ __half g_Vh[BATCH * SEQ * HD];            // V / colsum, fp16

// ---------------- cp.async helpers -----------------------------------------
__device__ __forceinline__ void cp16(void* smem_dst, const void* gsrc) {
    uint32_t s = (uint32_t)__cvta_generic_to_shared(smem_dst);
    asm volatile("cp.async.cg.shared.global [%0], [%1], 16;" :: "r"(s), "l"(gsrc));
}
__device__ __forceinline__ void cp_commit() {
    asm volatile("cp.async.commit_group;" ::: "memory");
}
template<int N> __device__ __forceinline__ void cp_wait() {
    asm volatile("cp.async.wait_group %0;" :: "n"(N) : "memory");
}

// ---------------- P1: Q/K -> fp16, zero colsum, detect mask dtype ----------
__global__ void prologue_kernel(const float4* __restrict__ Q,
                                const float4* __restrict__ K,
                                const int* __restrict__ mask_i) {
    const int n4 = BATCH * SEQ * HD / 4;
    int i = blockIdx.x * 256 + threadIdx.x;
    if (i < n4) {
        float4 v = Q[i];
        __half2* d = reinterpret_cast<__half2*>(g_Qh);
        d[2 * i]     = __floats2half2_rn(v.x, v.y);
        d[2 * i + 1] = __floats2half2_rn(v.z, v.w);
    } else {
        int j = i - n4;
        float4 v = K[j];
        __half2* d = reinterpret_cast<__half2*>(g_Kh);
        d[2 * j]     = __floats2half2_rn(v.x, v.y);
        d[2 * j + 1] = __floats2half2_rn(v.z, v.w);
    }
    if (i < BATCH * SEQ) g_colsum[i] = 0.0f;
    // int32 bool mask -> words in {0,1}; u8 mask read as int32 -> bytes packed
    if (i < 16384) { if ((unsigned)mask_i[i] > 1u) g_mask_is_u8 = 1; }
}

// ---------------- P2: Vh = fp16(V / colsum), same [b][k][d] layout ----------
__global__ void scale_v_kernel(const float4* __restrict__ V) {
    int i = blockIdx.x * blockDim.x + threadIdx.x;   // float4 index
    int row = i >> 5;                                // (b*SEQ + k)
    float inv = 1.0f / g_colsum[row];
    float4 v = V[i];
    __half2* dst = reinterpret_cast<__half2*>(g_Vh);
    dst[i * 2 + 0] = __floats2half2_rn(v.x * inv, v.y * inv);
    dst[i * 2 + 1] = __floats2half2_rn(v.z * inv, v.w * inv);
}

// ---------------------------------------------------------------------------
// K1: Eh[b,q,k] = half(exp( mask ? 1e-9 : (Q.K^T)/sqrt(D) ))
//     colsum[b,k] += sum_q float(Eh)        (denominator matches numerators)
// Tile 128(q) x 128(k), full-depth resident fp16 operands, 8 warps 64x32.
// Epilogue: 4 k-columns per thread, vectorized mask read + 8B E store,
// smem-reduced colsum.
// ---------------------------------------------------------------------------
constexpr int BM1 = 128, BN1 = 128;
constexpr int LD1 = 136;                        // halves; 272B rows
constexpr int QS_H   = BM1 * LD1;               // 17408 halves
constexpr int SMEM1  = 2 * QS_H * 2;            // Q + K tiles = 69632 B
constexpr int C_LD   = 132;                     // fp32 staging stride

__global__ __launch_bounds__(256, 2) void qk_exp_kernel(const void* __restrict__ mask)
{
    extern __shared__ __half hsm[];
    __shared__ float csum[BN1];
    __half* Qs = hsm;
    __half* Ks = hsm + QS_H;

    const int b  = blockIdx.z;
    const int q0 = blockIdx.y * BM1;
    const int k0 = blockIdx.x * BN1;
    const int tid  = threadIdx.x;
    const int warp = tid >> 5;
    const int warp_m = warp >> 2;   // 0..1 -> 64 q rows
    const int warp_n = warp & 3;    // 0..3 -> 32 k cols

    const __half* Qb = g_Qh + ((size_t)b * SEQ + q0) * HD;
    const __half* Kb = g_Kh + ((size_t)b * SEQ + k0) * HD;

    #pragma unroll
    for (int it = 0; it < 8; it++) {
        int idx = tid + it * 256;
        int r = idx >> 4, c8 = (idx & 15) << 3;
        cp16(Qs + r * LD1 + c8, Qb + (size_t)r * HD + c8);
    }
    #pragma unroll
    for (int it = 0; it < 8; it++) {
        int idx = tid + it * 256;
        int r = idx >> 4, c8 = (idx & 15) << 3;
        cp16(Ks + r * LD1 + c8, Kb + (size_t)r * HD + c8);
    }
    cp_commit(); cp_wait<0>();
    __syncthreads();

    wmma::fragment<wmma::accumulator, 16, 16, 16, float> acc[4][2];
    #pragma unroll
    for (int i = 0; i < 4; i++)
        #pragma unroll
        for (int j = 0; j < 2; j++)
            wmma::fill_fragment(acc[i][j], 0.0f);

    #pragma unroll
    for (int kk = 0; kk < HD; kk += 16) {
        wmma::fragment<wmma::matrix_a, 16, 16, 16, __half, wmma::row_major> af[4];
        wmma::fragment<wmma::matrix_b, 16, 16, 16, __half, wmma::col_major> bf[2];
        #pragma unroll
        for (int i = 0; i < 4; i++)
            wmma::load_matrix_sync(af[i], Qs + (warp_m * 64 + i * 16) * LD1 + kk, LD1);
        #pragma unroll
        for (int j = 0; j < 2; j++)
            wmma::load_matrix_sync(bf[j], Ks + (warp_n * 32 + j * 16) * LD1 + kk, LD1);
        #pragma unroll
        for (int i = 0; i < 4; i++)
            #pragma unroll
            for (int j = 0; j < 2; j++)
                wmma::mma_sync(acc[i][j], af[i], bf[j], acc[i][j]);
    }
    __syncthreads();   // tiles dead; reuse smem for fp32 staging

    float* C = reinterpret_cast<float*>(hsm);
    #pragma unroll
    for (int i = 0; i < 4; i++)
        #pragma unroll
        for (int j = 0; j < 2; j++)
            wmma::store_matrix_sync(C + (warp_m * 64 + i * 16) * C_LD + warp_n * 32 + j * 16,
                                    acc[i][j], C_LD, wmma::mem_row_major);
    if (tid < BN1) csum[tid] = 0.0f;
    __syncthreads();

    // Epilogue: thread owns 4 k-cols c4 = (tid&31)*4; rows r = it*8 + (tid>>5).
    const float scale = 0.088388347648318447f;   // 1/sqrt(128)
    const size_t moff = ((size_t)b * SEQ + q0) * SEQ + k0;
    const int*           mbi = reinterpret_cast<const int*>(mask) + moff;
    const unsigned char* mb8 = reinterpret_cast<const unsigned char*>(mask) + moff;
    const bool is_u8 = (g_mask_is_u8 != 0);
    __half* Eb = g_Eh + moff;

    const int c4 = (tid & 31) * 4;
    const int r0 = tid >> 5;
    float l0 = 0.f, l1 = 0.f, l2 = 0.f, l3 = 0.f;

    #pragma unroll
    for (int it = 0; it < 16; it++) {
        int r = it * 8 + r0;
        size_t row = (size_t)r * SEQ;
        float4 sv = *reinterpret_cast<const float4*>(&C[r * C_LD + c4]);
        int m0, m1, m2, m3;
        if (is_u8) {
            uchar4 mu = *reinterpret_cast<const uchar4*>(mb8 + row + c4);
            m0 = mu.x; m1 = mu.y; m2 = mu.z; m3 = mu.w;
        } else {
            int4 mi = *reinterpret_cast<const int4*>(mbi + row + c4);
            m0 = mi.x; m1 = mi.y; m2 = mi.z; m3 = mi.w;
        }
        float e0 = __expf(m0 ? 1e-9f : sv.x * scale);
        float e1 = __expf(m1 ? 1e-9f : sv.y * scale);
        float e2 = __expf(m2 ? 1e-9f : sv.z * scale);
        float e3 = __expf(m3 ? 1e-9f : sv.w * scale);
        __half2 h01 = __floats2half2_rn(e0, e1);
        __half2 h23 = __floats2half2_rn(e2, e3);
        uint2 st;
        st.x = *reinterpret_cast<uint32_t*>(&h01);
        st.y = *reinterpret_cast<uint32_t*>(&h23);
        *reinterpret_cast<uint2*>(Eb + row + c4) = st;
        // denominator = sum of the half-rounded numerators
        l0 += __low2float(h01); l1 += __high2float(h01);
        l2 += __low2float(h23); l3 += __high2float(h23);
    }
    atomicAdd(&csum[c4 + 0], l0);
    atomicAdd(&csum[c4 + 1], l1);
    atomicAdd(&csum[c4 + 2], l2);
    atomicAdd(&csum[c4 + 3], l3);
    __syncthreads();
    if (tid < BN1) atomicAdd(&g_colsum[b * SEQ + k0 + tid], csum[tid]);
}

// ---------------------------------------------------------------------------
// K2: out[b,q,d] = sum_k Eh[b,q,k] * Vh[b,k,d]   (Vh pre-scaled by 1/colsum)
// Tile 128(q) x 128(d), K chunks of 64, 2-stage cp.async, 8 warps 64x32.
// ---------------------------------------------------------------------------
constexpr int BM2 = 128, BK2 = 64;
constexpr int LDE2 = 72;                         // halves
constexpr int LDV2 = 136;                        // halves
constexpr int ST2_H  = BM2 * LDE2 + BK2 * LDV2;  // 17920 halves per stage
constexpr int SMEM2  = ST2_H * 2 * 2;            // 71680 B

__global__ __launch_bounds__(256, 2) void pv_kernel(float* __restrict__ out)
{
    extern __shared__ __half hsm[];

    const int b  = blockIdx.y;
    const int q0 = blockIdx.x * BM2;
    const int tid  = threadIdx.x;
    const int warp = tid >> 5;
    const int warp_m = warp >> 2;   // 0..1 -> 64 q rows
    const int warp_n = warp & 3;    // 0..3 -> 32 d cols

    const __half* Eb = g_Eh + ((size_t)b * SEQ + q0) * SEQ;
    const __half* Vb = g_Vh + (size_t)b * SEQ * HD;

    wmma::fragment<wmma::accumulator, 16, 16, 16, float> acc[4][2];
    #pragma unroll
    for (int i = 0; i < 4; i++)
        #pragma unroll
        for (int j = 0; j < 2; j++)
            wmma::fill_fragment(acc[i][j], 0.0f);

    auto load_stage = [&](int s, int kc) {
        __half* Es = hsm + s * ST2_H;
        __half* Vs = Es + BM2 * LDE2;
        #pragma unroll
        for (int it = 0; it < 4; it++) {               // E 128 x 64 halves
            int idx = tid + it * 256;
            int r = idx >> 3, c8 = (idx & 7) << 3;
            cp16(Es + r * LDE2 + c8, Eb + (size_t)r * SEQ + kc + c8);
        }
        #pragma unroll
        for (int it = 0; it < 4; it++) {               // V 64 x 128 halves
            int idx = tid + it * 256;
            int r = idx >> 4, c8 = (idx & 15) << 3;
            cp16(Vs + r * LDV2 + c8, Vb + (size_t)(kc + r) * HD + c8);
        }
    };

    load_stage(0, 0); cp_commit();
    for (int c = 0; c < SEQ / BK2; c++) {
        if (c < SEQ / BK2 - 1) { load_stage((c + 1) & 1, (c + 1) * BK2); cp_commit(); cp_wait<1>(); }
        else                   { cp_wait<0>(); }
        __syncthreads();

        __half* Es = hsm + (c & 1) * ST2_H;
        __half* Vs = Es + BM2 * LDE2;
        #pragma unroll
        for (int kk = 0; kk < BK2; kk += 16) {
            wmma::fragment<wmma::matrix_a, 16, 16, 16, __half, wmma::row_major> af[4];
            wmma::fragment<wmma::matrix_b, 16, 16, 16, __half, wmma::row_major> bf[2];
            #pragma unroll
            for (int i = 0; i < 4; i++)
                wmma::load_matrix_sync(af[i], Es + (warp_m * 64 + i * 16) * LDE2 + kk, LDE2);
            #pragma unroll
            for (int j = 0; j < 2; j++)
                wmma::load_matrix_sync(bf[j], Vs + kk * LDV2 + warp_n * 32 + j * 16, LDV2);
            #pragma unroll
            for (int i = 0; i < 4; i++)
                #pragma unroll
                for (int j = 0; j < 2; j++)
                    wmma::mma_sync(acc[i][j], af[i], bf[j], acc[i][j]);
        }
        __syncthreads();
    }

    #pragma unroll
    for (int i = 0; i < 4; i++)
        #pragma unroll
        for (int j = 0; j < 2; j++) {
            float* dst = out + ((size_t)b * SEQ + q0 + warp_m * 64 + i * 16) * HD
                             + warp_n * 32 + j * 16;
            wmma::store_matrix_sync(dst, acc[i][j], HD, wmma::mem_row_major);
        }
}

// ---------------------------------------------------------------------------
extern "C" void kernel_launch(void* const* d_in, const int* in_sizes, int n_in,
                              void* d_out, int out_size) {
    const float* Q = (const float*)d_in[0];
    const float* K = (const float*)d_in[1];
    const float* V = (const float*)d_in[2];
    const void*  mask = d_in[3];
    float* out = (float*)d_out;

    cudaFuncSetAttribute(qk_exp_kernel, cudaFuncAttributeMaxDynamicSharedMemorySize, SMEM1);
    cudaFuncSetAttribute(pv_kernel,     cudaFuncAttributeMaxDynamicSharedMemorySize, SMEM2);

    const int n4 = BATCH * SEQ * HD / 4;   // float4 count per tensor

    prologue_kernel<<<2 * n4 / 256, 256>>>((const float4*)Q, (const float4*)K, (const int*)mask);
    qk_exp_kernel<<<dim3(SEQ / BN1, SEQ / BM1, BATCH), 256, SMEM1>>>(mask);
    scale_v_kernel<<<n4 / 256, 256>>>((const float4*)V);
    pv_kernel<<<dim3(SEQ / BM2, BATCH), 256, SMEM2>>>(out);
}